// round 3
// baseline (speedup 1.0000x reference)
#include <cuda_runtime.h>
#include <cuda_bf16.h>
#include <stdint.h>

// Problem constants
#define B_    64
#define MAXT  511
#define TP1   512
#define S_    1024
#define H_    4096
#define NA_   4

// Tiling
#define TILE_M 128
#define TILE_N 128
#define TILE_K 64
#define KPAD   72        // padded K stride (bf16): 144B rows -> conflict-free frags, 16B aligned
#define NTILES_T 4
#define NBLOCKS (B_ * NTILES_T)
#define NKC   (S_ / TILE_K)            // 16
#define NHC   (H_ / TILE_N)            // 32
#define NIT   (NHC * NKC)              // 512

// Dynamic smem layout (bytes)
#define AS_ELEMS (2 * TILE_M * KPAD)
#define BS_ELEMS (2 * TILE_N * KPAD)
#define SMEM_BYTES ((AS_ELEMS + BS_ELEMS) * 2 + 4 * TILE_M * 4 * 4 + 32)

// Scratch (static device allocations are allowed)
__device__ __nv_bfloat16 g_s_bf[(size_t)B_ * TP1 * S_];   // 64 MB
__device__ __nv_bfloat16 g_w1t[(size_t)H_ * S_];          // 8 MB, W1^T [H][S]
__device__ float g_partial[NBLOCKS];

// ---------------------------------------------------------------------------
__global__ void cvt_s_kernel(const float4* __restrict__ s)
{
    int i = blockIdx.x * blockDim.x + threadIdx.x;
    float4 v = s[i];
    __nv_bfloat162 lo = __floats2bfloat162_rn(v.x, v.y);
    __nv_bfloat162 hi = __floats2bfloat162_rn(v.z, v.w);
    uint2 u;
    u.x = *reinterpret_cast<unsigned int*>(&lo);
    u.y = *reinterpret_cast<unsigned int*>(&hi);
    reinterpret_cast<uint2*>(g_s_bf)[i] = u;
}

__global__ void cvt_w1t_kernel(const float* __restrict__ W1)
{
    int i = blockIdx.x * blockDim.x + threadIdx.x;
    int h = i >> 10;
    int k = i & (S_ - 1);
    g_w1t[i] = __float2bfloat16(W1[(size_t)k * H_ + h]);
}

// ---------------------------------------------------------------------------
__device__ __forceinline__ void mma16816(float c[4], const uint32_t a[4], const uint32_t b[2])
{
    asm volatile(
        "mma.sync.aligned.m16n8k16.row.col.f32.bf16.bf16.f32 "
        "{%0,%1,%2,%3}, {%4,%5,%6,%7}, {%8,%9}, {%0,%1,%2,%3};\n"
        : "+f"(c[0]), "+f"(c[1]), "+f"(c[2]), "+f"(c[3])
        : "r"(a[0]), "r"(a[1]), "r"(a[2]), "r"(a[3]), "r"(b[0]), "r"(b[1]));
}

__device__ __forceinline__ void cp_async16(uint32_t saddr, const void* gptr)
{
    asm volatile("cp.async.cg.shared.global [%0], [%1], 16;\n" :: "r"(saddr), "l"(gptr));
}
#define CP_COMMIT() asm volatile("cp.async.commit_group;\n")
#define CP_WAIT(n)  asm volatile("cp.async.wait_group %0;\n" :: "n"(n))

// ---------------------------------------------------------------------------
// Fused kernel. Grid (NTILES_T, B_), 256 threads = 8 warps (2m x 4n).
// Warp tile 64x32 of m16n8k16; logits fused in epilogue; per-block partial.
// ---------------------------------------------------------------------------
__global__ __launch_bounds__(256, 1)
void traj_main(const float* __restrict__ b1,
               const float* __restrict__ W2,
               const float* __restrict__ b2,
               const int*   __restrict__ actions,
               const int*   __restrict__ lengths)
{
    const int b    = blockIdx.y;
    const int tile = blockIdx.x;
    const int t0   = tile * TILE_M;
    const int len  = lengths[b];
    const int pid  = b * NTILES_T + tile;

    if (t0 >= len) {
        if (threadIdx.x == 0) g_partial[pid] = 0.0f;
        return;
    }

    extern __shared__ __align__(16) char smem_raw[];
    __nv_bfloat16* As = reinterpret_cast<__nv_bfloat16*>(smem_raw);          // [2][128][KPAD]
    __nv_bfloat16* Bs = As + AS_ELEMS;                                       // [2][128][KPAD]
    float* plog = reinterpret_cast<float*>(Bs + BS_ELEMS);                   // [4][128][4]
    float* red  = plog + 4 * TILE_M * 4;

    const uint32_t sAs = (uint32_t)__cvta_generic_to_shared(As);
    const uint32_t sBs = (uint32_t)__cvta_generic_to_shared(Bs);

    const int tid    = threadIdx.x;
    const int wid    = tid >> 5;
    const int lane   = tid & 31;
    const int warp_m = wid >> 2;
    const int warp_n = wid & 3;
    const int g      = lane >> 2;
    const int t4     = lane & 3;

    float logit_local[8][4];
#pragma unroll
    for (int r = 0; r < 8; r++)
#pragma unroll
        for (int j = 0; j < 4; j++) logit_local[r][j] = 0.0f;

    const __nv_bfloat16* sbase = g_s_bf + ((size_t)b * TP1 + t0) * S_;

    // Per-thread staging coords: 4 chunks of 16B per matrix per stage
    int srow[4], scol[4];
#pragma unroll
    for (int i = 0; i < 4; i++) {
        int chunk = tid + 256 * i;      // 0..1023
        srow[i] = chunk >> 3;
        scol[i] = (chunk & 7) * 8;
    }

    // stage(it, buf): loads A chunk (kc) and B chunk (hc,kc) into buffer buf
    auto stage = [&](int it, int buf) {
        const int hc = it >> 4;
        const int kc = it & 15;
        const int kbase = kc * TILE_K;
        const int hbase = hc * TILE_N;
#pragma unroll
        for (int i = 0; i < 4; i++) {
            int row = srow[i], cc = scol[i];
            cp_async16(sAs + (uint32_t)(((buf * TILE_M + row) * KPAD + cc) * 2),
                       sbase + (size_t)row * S_ + kbase + cc);
            cp_async16(sBs + (uint32_t)(((buf * TILE_N + row) * KPAD + cc) * 2),
                       g_w1t + (size_t)(hbase + row) * S_ + kbase + cc);
        }
    };

    float C[4][4][4];

    // Pipeline prologue
    stage(0, 0);
    CP_COMMIT();

    for (int it = 0; it < NIT; it++) {
        const int kc  = it & 15;
        const int buf = it & 1;

        if (kc == 0) {
#pragma unroll
            for (int mt = 0; mt < 4; mt++)
#pragma unroll
                for (int nt = 0; nt < 4; nt++)
#pragma unroll
                    for (int e = 0; e < 4; e++) C[mt][nt][e] = 0.0f;
        }

        if (it + 1 < NIT) {
            stage(it + 1, buf ^ 1);
            CP_COMMIT();
            CP_WAIT(1);
        } else {
            CP_WAIT(0);
        }
        __syncthreads();

        // Compute from buffer `buf`
        const __nv_bfloat16* Ab = As + buf * TILE_M * KPAD;
        const __nv_bfloat16* Bb = Bs + buf * TILE_N * KPAD;
#pragma unroll
        for (int ks = 0; ks < TILE_K / 16; ks++) {
            const int k0 = ks * 16;
            uint32_t a[4][4], bb[4][2];
#pragma unroll
            for (int mt = 0; mt < 4; mt++) {
                int row = warp_m * 64 + mt * 16;
                a[mt][0] = *reinterpret_cast<const uint32_t*>(&Ab[(row + g    ) * KPAD + k0 + t4 * 2    ]);
                a[mt][1] = *reinterpret_cast<const uint32_t*>(&Ab[(row + g + 8) * KPAD + k0 + t4 * 2    ]);
                a[mt][2] = *reinterpret_cast<const uint32_t*>(&Ab[(row + g    ) * KPAD + k0 + t4 * 2 + 8]);
                a[mt][3] = *reinterpret_cast<const uint32_t*>(&Ab[(row + g + 8) * KPAD + k0 + t4 * 2 + 8]);
            }
#pragma unroll
            for (int nt = 0; nt < 4; nt++) {
                int col = warp_n * 32 + nt * 8 + g;
                bb[nt][0] = *reinterpret_cast<const uint32_t*>(&Bb[col * KPAD + k0 + t4 * 2    ]);
                bb[nt][1] = *reinterpret_cast<const uint32_t*>(&Bb[col * KPAD + k0 + t4 * 2 + 8]);
            }
#pragma unroll
            for (int mt = 0; mt < 4; mt++)
#pragma unroll
                for (int nt = 0; nt < 4; nt++)
                    mma16816(C[mt][nt], a[mt], bb[nt]);
        }
        __syncthreads();   // protect buf from being restaged next iteration

        // Epilogue at the end of each hc chunk: relu(C+b1) * W2[:, 0:4]
        if (kc == 15) {
            const int hbase = (it >> 4) * TILE_N;
#pragma unroll
            for (int nt = 0; nt < 4; nt++) {
                const int col0 = hbase + warp_n * 32 + nt * 8 + t4 * 2;
                float2 b1v = *reinterpret_cast<const float2*>(&b1[col0]);
                float4 w2a = *reinterpret_cast<const float4*>(&W2[(size_t)col0 * 32]);
                float4 w2b = *reinterpret_cast<const float4*>(&W2[(size_t)(col0 + 1) * 32]);
#pragma unroll
                for (int mt = 0; mt < 4; mt++) {
#pragma unroll
                    for (int half = 0; half < 2; half++) {
                        float v0 = fmaxf(C[mt][nt][half * 2 + 0] + b1v.x, 0.0f);
                        float v1 = fmaxf(C[mt][nt][half * 2 + 1] + b1v.y, 0.0f);
                        int rs = mt * 2 + half;
                        logit_local[rs][0] += v0 * w2a.x + v1 * w2b.x;
                        logit_local[rs][1] += v0 * w2a.y + v1 * w2b.y;
                        logit_local[rs][2] += v0 * w2a.z + v1 * w2b.z;
                        logit_local[rs][3] += v0 * w2a.w + v1 * w2b.w;
                    }
                }
            }
        }
    }

    // Reduce per-thread logits across the 4 lanes of each group -> plog[warp_n]
#pragma unroll
    for (int mt = 0; mt < 4; mt++) {
#pragma unroll
        for (int half = 0; half < 2; half++) {
            int rs  = mt * 2 + half;
            int row = warp_m * 64 + mt * 16 + half * 8 + g;
#pragma unroll
            for (int j = 0; j < 4; j++) {
                float v = logit_local[rs][j];
                v += __shfl_xor_sync(0xffffffffu, v, 1);
                v += __shfl_xor_sync(0xffffffffu, v, 2);
                if (t4 == 0) plog[(warp_n * TILE_M + row) * 4 + j] = v;
            }
        }
    }
    __syncthreads();

    // Per-row logsumexp + gather + mask
    float contrib = 0.0f;
    if (tid < TILE_M) {
        int row = tid;
        int t   = t0 + row;
        float l[4];
#pragma unroll
        for (int j = 0; j < 4; j++)
            l[j] = b2[j] + plog[(0 * TILE_M + row) * 4 + j] + plog[(1 * TILE_M + row) * 4 + j]
                         + plog[(2 * TILE_M + row) * 4 + j] + plog[(3 * TILE_M + row) * 4 + j];
        if (t < len) {
            int act = actions[b * MAXT + t];
            float mx  = fmaxf(fmaxf(l[0], l[1]), fmaxf(l[2], l[3]));
            float lse = mx + logf(expf(l[0] - mx) + expf(l[1] - mx) + expf(l[2] - mx) + expf(l[3] - mx));
            contrib = l[act] - lse;
        }
    }
#pragma unroll
    for (int o = 16; o > 0; o >>= 1) contrib += __shfl_xor_sync(0xffffffffu, contrib, o);
    if (lane == 0) red[wid] = contrib;
    __syncthreads();
    if (tid == 0) {
        float s = 0.0f;
        for (int w = 0; w < 8; w++) s += red[w];
        g_partial[pid] = s;
    }
}

// ---------------------------------------------------------------------------
__global__ void finalize_kernel(float* __restrict__ out)
{
    int tid = threadIdx.x;   // 256 threads
    float v = g_partial[tid];
#pragma unroll
    for (int o = 16; o > 0; o >>= 1) v += __shfl_xor_sync(0xffffffffu, v, o);
    __shared__ float red[8];
    if ((tid & 31) == 0) red[tid >> 5] = v;
    __syncthreads();
    if (tid == 0) {
        float s = 0.0f;
        for (int w = 0; w < 8; w++) s += red[w];
        out[0] = -s;
    }
}

// ---------------------------------------------------------------------------
extern "C" void kernel_launch(void* const* d_in, const int* in_sizes, int n_in,
                              void* d_out, int out_size)
{
    const float* s       = (const float*)d_in[0];
    const int*   actions = (const int*)  d_in[1];
    const int*   lengths = (const int*)  d_in[2];
    const float* W1      = (const float*)d_in[3];
    const float* b1      = (const float*)d_in[4];
    const float* W2      = (const float*)d_in[5];
    const float* b2      = (const float*)d_in[6];
    float* out = (float*)d_out;

    cudaFuncSetAttribute(traj_main, cudaFuncAttributeMaxDynamicSharedMemorySize, SMEM_BYTES);

    cvt_s_kernel<<<32768, 256>>>((const float4*)s);
    cvt_w1t_kernel<<<(H_ * S_) / 256, 256>>>(W1);
    traj_main<<<dim3(NTILES_T, B_), 256, SMEM_BYTES>>>(b1, W2, b2, actions, lengths);
    finalize_kernel<<<1, 256>>>(out);
}

// round 8
// speedup vs baseline: 1.7177x; 1.7177x over previous
#include <cuda_runtime.h>
#include <cuda_bf16.h>
#include <cuda_fp8.h>
#include <stdint.h>

// Problem constants
#define B_    64
#define MAXT  511
#define TP1   512
#define S_    1024
#define H_    4096

// Tiling (fp8 legacy mma m16n8k32)
#define TILE_M 128
#define TILE_N 128          // H columns per block
#define TILE_KB 128         // K bytes per stage (128 fp8 elems)
#define NKT   (S_ / TILE_KB)   // 8 k-iterations
#define NHC   (H_ / TILE_N)    // 32 H-chunks
#define NTILES_T 4
#define NTILE (B_ * NTILES_T)  // 256 (b,t-tile) units

// smem: 2 stages x (A 16KB + B 16KB) + plog
#define A_BYTES   (TILE_M * TILE_KB)          // 16384
#define STAGE_BYTES (2 * A_BYTES)             // 32768
#define OFF_PLOG  (2 * STAGE_BYTES)           // 65536
#define PLOG_BYTES (4 * TILE_M * 4 * 4)       // 8192
#define SMEM_BYTES (OFF_PLOG + PLOG_BYTES + 128)

// Scratch
__device__ uint8_t g_s_f8[(size_t)B_ * TP1 * S_];    // 32 MB, s in e4m3
__device__ uint8_t g_w1t[(size_t)H_ * S_];           // 4 MB, W1^T [H][S] e4m3
__device__ float4  g_plog[(size_t)NTILE * NHC * TILE_M];  // 16 MB partial logits
__device__ float   g_partial[NTILE];

// ---------------------------------------------------------------------------
__device__ __forceinline__ void cp_async16(uint32_t saddr, const void* gptr) {
    asm volatile("cp.async.cg.shared.global [%0], [%1], 16;\n" :: "r"(saddr), "l"(gptr));
}
#define CP_COMMIT() asm volatile("cp.async.commit_group;\n")
#define CP_WAIT(n)  asm volatile("cp.async.wait_group %0;\n" :: "n"(n))

// fp8 e4m3 mma, fp32 accumulate (legacy tensor path, sm_89+)
__device__ __forceinline__ void mma_fp8(float c[4], const uint32_t a[4], const uint32_t b[2])
{
    asm volatile(
        "mma.sync.aligned.m16n8k32.row.col.f32.e4m3.e4m3.f32 "
        "{%0,%1,%2,%3}, {%4,%5,%6,%7}, {%8,%9}, {%0,%1,%2,%3};\n"
        : "+f"(c[0]), "+f"(c[1]), "+f"(c[2]), "+f"(c[3])
        : "r"(a[0]), "r"(a[1]), "r"(a[2]), "r"(a[3]), "r"(b[0]), "r"(b[1]));
}

// ---------------------------------------------------------------------------
// Converts
// ---------------------------------------------------------------------------
__global__ void cvt_s_kernel(const float4* __restrict__ s)
{
    int i = blockIdx.x * blockDim.x + threadIdx.x;   // N/4 threads
    float4 v = s[i];
    __nv_fp8x2_storage_t lo = __nv_cvt_float2_to_fp8x2(make_float2(v.x, v.y), __NV_SATFINITE, __NV_E4M3);
    __nv_fp8x2_storage_t hi = __nv_cvt_float2_to_fp8x2(make_float2(v.z, v.w), __NV_SATFINITE, __NV_E4M3);
    reinterpret_cast<uint32_t*>(g_s_f8)[i] = (uint32_t)lo | ((uint32_t)hi << 16);
}

__global__ void cvt_w1t_kernel(const float* __restrict__ W1)
{
    __shared__ float tile[32][33];
    const int h0 = blockIdx.x * 32;
    const int k0 = blockIdx.y * 32;
    const int tx = threadIdx.x;      // 32
    const int ty = threadIdx.y;      // 8
#pragma unroll
    for (int i = 0; i < 32; i += 8)
        tile[ty + i][tx] = W1[(size_t)(k0 + ty + i) * H_ + h0 + tx];
    __syncthreads();
#pragma unroll
    for (int i = 0; i < 32; i += 8)
        g_w1t[(size_t)(h0 + ty + i) * S_ + k0 + tx] =
            (uint8_t)__nv_cvt_float_to_fp8(tile[tx][ty + i], __NV_SATFINITE, __NV_E4M3);
}

// ---------------------------------------------------------------------------
// Main GEMM+epilogue unit kernel.
// Grid (NHC=32, NTILES_T=4, B_=64); 256 threads = 8 warps (2m x 4n).
// Unit: C[128m x 128h] = s_tile[128x1024] @ W1t_chunk[128x1024]^T (fp8),
// then partial logits via relu(C+b1) @ W2[:, :4] -> g_plog[unit].
// ---------------------------------------------------------------------------
__global__ __launch_bounds__(256, 1)
void traj_main(const float* __restrict__ b1,
               const float* __restrict__ W2,
               const int*   __restrict__ lengths)
{
    const int hc   = blockIdx.x;
    const int tile = blockIdx.y;
    const int b    = blockIdx.z;
    const int t0   = tile * TILE_M;
    if (t0 >= lengths[b]) return;

    extern __shared__ __align__(16) char smem_raw[];
    char* sm = (char*)(((uintptr_t)smem_raw + 127) & ~(uintptr_t)127);
    const uint32_t sb = (uint32_t)__cvta_generic_to_shared(sm);

    const int tid    = threadIdx.x;
    const int wid    = tid >> 5;
    const int lane   = tid & 31;
    const int warp_m = wid >> 2;      // 0..1
    const int warp_n = wid & 3;       // 0..3
    const int g      = lane >> 2;     // 0..7
    const int t4     = lane & 3;      // 0..3

    // Staging plan: 8 granules of 16B per thread per stage (A: 1024, B: 1024)
    uint32_t soff[8];
    const uint8_t* gptr[8];
    const uint8_t* sbase = g_s_f8 + ((size_t)b * TP1 + t0) * S_;
    const int hbase = hc * TILE_N;
#pragma unroll
    for (int i = 0; i < 8; i++) {
        int gi = tid + 256 * i;          // 0..2047
        if (gi < 1024) {
            int row = gi >> 3, c = gi & 7;
            soff[i] = (uint32_t)((row << 7) + ((c ^ (row & 7)) << 4));
            gptr[i] = sbase + (size_t)row * S_ + c * 16;
        } else {
            int gb = gi - 1024;
            int row = gb >> 3, c = gb & 7;
            soff[i] = (uint32_t)(A_BYTES + (row << 7) + ((c ^ (row & 7)) << 4));
            gptr[i] = g_w1t + (size_t)(hbase + row) * S_ + c * 16;
        }
    }

    auto stage = [&](int kt) {
        const uint32_t base = sb + (kt & 1) * STAGE_BYTES;
        const int koff = kt * TILE_KB;
#pragma unroll
        for (int i = 0; i < 8; i++)
            cp_async16(base + soff[i], gptr[i] + koff);
    };

    float C[4][4][4];
#pragma unroll
    for (int mt = 0; mt < 4; mt++)
#pragma unroll
        for (int nt = 0; nt < 4; nt++)
#pragma unroll
            for (int e = 0; e < 4; e++) C[mt][nt][e] = 0.0f;

    stage(0); CP_COMMIT();

    for (int kt = 0; kt < NKT; kt++) {
        if (kt + 1 < NKT) { stage(kt + 1); CP_COMMIT(); CP_WAIT(1); }
        else              { CP_WAIT(0); }
        __syncthreads();

        const char* Ab = sm + (kt & 1) * STAGE_BYTES;
        const char* Bb = Ab + A_BYTES;
#pragma unroll
        for (int ks = 0; ks < 4; ks++) {
            const uint32_t swz0 = (uint32_t)(((2 * ks    ) ^ g) << 4) + t4 * 4;
            const uint32_t swz1 = (uint32_t)(((2 * ks + 1) ^ g) << 4) + t4 * 4;
            uint32_t a[4][4], bb[4][2];
#pragma unroll
            for (int mt = 0; mt < 4; mt++) {
                const int r0 = warp_m * 64 + mt * 16 + g;
                a[mt][0] = *reinterpret_cast<const uint32_t*>(Ab + ((r0    ) << 7) + swz0);
                a[mt][1] = *reinterpret_cast<const uint32_t*>(Ab + ((r0 + 8) << 7) + swz0);
                a[mt][2] = *reinterpret_cast<const uint32_t*>(Ab + ((r0    ) << 7) + swz1);
                a[mt][3] = *reinterpret_cast<const uint32_t*>(Ab + ((r0 + 8) << 7) + swz1);
            }
#pragma unroll
            for (int nt = 0; nt < 4; nt++) {
                const int col = warp_n * 32 + nt * 8 + g;
                bb[nt][0] = *reinterpret_cast<const uint32_t*>(Bb + (col << 7) + swz0);
                bb[nt][1] = *reinterpret_cast<const uint32_t*>(Bb + (col << 7) + swz1);
            }
#pragma unroll
            for (int mt = 0; mt < 4; mt++)
#pragma unroll
                for (int nt = 0; nt < 4; nt++)
                    mma_fp8(C[mt][nt], a[mt], bb[nt]);
        }
        __syncthreads();
    }

    // Epilogue: relu(C + b1) * W2[:, 0:4] -> per-thread logits
    float lg[8][4];
#pragma unroll
    for (int r = 0; r < 8; r++)
#pragma unroll
        for (int j = 0; j < 4; j++) lg[r][j] = 0.0f;

#pragma unroll
    for (int nt = 0; nt < 4; nt++) {
        const int h0 = hbase + warp_n * 32 + nt * 8 + t4 * 2;
        const float2 b1v = *reinterpret_cast<const float2*>(&b1[h0]);
        const float4 w2a = *reinterpret_cast<const float4*>(W2 + (size_t)h0 * 32);
        const float4 w2b = *reinterpret_cast<const float4*>(W2 + (size_t)(h0 + 1) * 32);
#pragma unroll
        for (int mt = 0; mt < 4; mt++) {
#pragma unroll
            for (int half = 0; half < 2; half++) {
                const float v0 = fmaxf(C[mt][nt][half * 2 + 0] + b1v.x, 0.0f);
                const float v1 = fmaxf(C[mt][nt][half * 2 + 1] + b1v.y, 0.0f);
                const int rs = mt * 2 + half;
                lg[rs][0] += v0 * w2a.x + v1 * w2b.x;
                lg[rs][1] += v0 * w2a.y + v1 * w2b.y;
                lg[rs][2] += v0 * w2a.z + v1 * w2b.z;
                lg[rs][3] += v0 * w2a.w + v1 * w2b.w;
            }
        }
    }

    // Reduce across t4 lanes, stash per warp_n, then sum 4 warp_n groups
    float* plog = (float*)(sm + OFF_PLOG);   // [4][128][4]
#pragma unroll
    for (int mt = 0; mt < 4; mt++) {
#pragma unroll
        for (int half = 0; half < 2; half++) {
            const int rs  = mt * 2 + half;
            const int row = warp_m * 64 + mt * 16 + half * 8 + g;
#pragma unroll
            for (int j = 0; j < 4; j++) {
                float v = lg[rs][j];
                v += __shfl_xor_sync(0xffffffffu, v, 1);
                v += __shfl_xor_sync(0xffffffffu, v, 2);
                if (t4 == 0) plog[(warp_n * TILE_M + row) * 4 + j] = v;
            }
        }
    }
    __syncthreads();

    if (tid < TILE_M) {
        const int row = tid;
        float4 o;
        o.x = plog[row * 4 + 0] + plog[(TILE_M + row) * 4 + 0] + plog[(2 * TILE_M + row) * 4 + 0] + plog[(3 * TILE_M + row) * 4 + 0];
        o.y = plog[row * 4 + 1] + plog[(TILE_M + row) * 4 + 1] + plog[(2 * TILE_M + row) * 4 + 1] + plog[(3 * TILE_M + row) * 4 + 1];
        o.z = plog[row * 4 + 2] + plog[(TILE_M + row) * 4 + 2] + plog[(2 * TILE_M + row) * 4 + 2] + plog[(3 * TILE_M + row) * 4 + 2];
        o.w = plog[row * 4 + 3] + plog[(TILE_M + row) * 4 + 3] + plog[(2 * TILE_M + row) * 4 + 3] + plog[(3 * TILE_M + row) * 4 + 3];
        const int unit = (b * NTILES_T + tile) * NHC + hc;
        g_plog[(size_t)unit * TILE_M + row] = o;
    }
}

// ---------------------------------------------------------------------------
// Loss: per (b,tile), sum partial logits over 32 hc, logsoftmax, gather, mask.
// Grid (NTILES_T, B_), 128 threads.
// ---------------------------------------------------------------------------
__global__ void loss_kernel(const float* __restrict__ b2,
                            const int*   __restrict__ actions,
                            const int*   __restrict__ lengths)
{
    const int tile = blockIdx.x;
    const int b    = blockIdx.y;
    const int pid  = b * NTILES_T + tile;
    const int t0   = tile * TILE_M;
    const int len  = lengths[b];

    float contrib = 0.0f;
    if (t0 < len) {
        const int row = threadIdx.x;
        const int t   = t0 + row;
        if (t < len) {
            float l0 = b2[0], l1 = b2[1], l2 = b2[2], l3 = b2[3];
            const float4* base = g_plog + (size_t)pid * NHC * TILE_M + row;
#pragma unroll
            for (int hc = 0; hc < NHC; hc++) {
                float4 p = base[hc * TILE_M];
                l0 += p.x; l1 += p.y; l2 += p.z; l3 += p.w;
            }
            const int act = actions[b * MAXT + t];
            const float mx  = fmaxf(fmaxf(l0, l1), fmaxf(l2, l3));
            const float lse = mx + logf(expf(l0 - mx) + expf(l1 - mx) + expf(l2 - mx) + expf(l3 - mx));
            const float la  = (act == 0) ? l0 : (act == 1) ? l1 : (act == 2) ? l2 : l3;
            contrib = la - lse;
        }
    }
#pragma unroll
    for (int o = 16; o > 0; o >>= 1) contrib += __shfl_xor_sync(0xffffffffu, contrib, o);
    __shared__ float red[4];
    if ((threadIdx.x & 31) == 0) red[threadIdx.x >> 5] = contrib;
    __syncthreads();
    if (threadIdx.x == 0)
        g_partial[pid] = red[0] + red[1] + red[2] + red[3];
}

// ---------------------------------------------------------------------------
__global__ void finalize_kernel(float* __restrict__ out)
{
    int tid = threadIdx.x;   // 256 threads
    float v = g_partial[tid];
#pragma unroll
    for (int o = 16; o > 0; o >>= 1) v += __shfl_xor_sync(0xffffffffu, v, o);
    __shared__ float red[8];
    if ((tid & 31) == 0) red[tid >> 5] = v;
    __syncthreads();
    if (tid == 0) {
        float s = 0.0f;
        for (int w = 0; w < 8; w++) s += red[w];
        out[0] = -s;
    }
}

// ---------------------------------------------------------------------------
extern "C" void kernel_launch(void* const* d_in, const int* in_sizes, int n_in,
                              void* d_out, int out_size)
{
    const float* s       = (const float*)d_in[0];
    const int*   actions = (const int*)  d_in[1];
    const int*   lengths = (const int*)  d_in[2];
    const float* W1      = (const float*)d_in[3];
    const float* b1      = (const float*)d_in[4];
    const float* W2      = (const float*)d_in[5];
    const float* b2      = (const float*)d_in[6];
    float* out = (float*)d_out;

    cudaFuncSetAttribute(traj_main, cudaFuncAttributeMaxDynamicSharedMemorySize, SMEM_BYTES);

    cvt_s_kernel<<<32768, 256>>>((const float4*)s);
    cvt_w1t_kernel<<<dim3(H_ / 32, S_ / 32), dim3(32, 8)>>>(W1);
    traj_main<<<dim3(NHC, NTILES_T, B_), 256, SMEM_BYTES>>>(b1, W2, lengths);
    loss_kernel<<<dim3(NTILES_T, B_), 128>>>(b2, actions, lengths);
    finalize_kernel<<<1, 256>>>(out);
}

// round 9
// speedup vs baseline: 2.0971x; 1.2209x over previous
#include <cuda_runtime.h>
#include <cuda_bf16.h>
#include <cuda_fp8.h>
#include <stdint.h>

// Problem constants
#define B_    64
#define MAXT  511
#define TP1   512
#define S_    1024
#define H_    4096

// Tiling (fp8 legacy mma m16n8k32)
#define TILE_M 128
#define TILE_N 128          // H columns per block
#define TILE_KB 128         // K bytes per stage
#define NKT   (S_ / TILE_KB)   // 8
#define NHC   (H_ / TILE_N)    // 32
#define NTILES_T 4
#define NTILE (B_ * NTILES_T)  // 256

// smem: 3 stages x (A 16KB + B 16KB) + plog
#define A_BYTES   (TILE_M * TILE_KB)          // 16384
#define STAGE_BYTES (2 * A_BYTES)             // 32768
#define NSTAGE 3
#define OFF_PLOG  (NSTAGE * STAGE_BYTES)      // 98304
#define PLOG_BYTES (4 * TILE_M * 4 * 4)       // 8192
#define SMEM_BYTES (OFF_PLOG + PLOG_BYTES + 128)

// Scratch
__device__ uint8_t g_s_f8[(size_t)B_ * TP1 * S_];    // 32 MB
__device__ uint8_t g_w1t[(size_t)H_ * S_];           // 4 MB, W1^T [H][S] e4m3
__device__ float4  g_plog[(size_t)NTILE * NHC * TILE_M];  // 16 MB
__device__ float   g_partial[NTILE];

// ---------------------------------------------------------------------------
__device__ __forceinline__ void cp_async16(uint32_t saddr, const void* gptr) {
    asm volatile("cp.async.cg.shared.global [%0], [%1], 16;\n" :: "r"(saddr), "l"(gptr));
}
#define CP_COMMIT() asm volatile("cp.async.commit_group;\n")
#define CP_WAIT(n)  asm volatile("cp.async.wait_group %0;\n" :: "n"(n))

__device__ __forceinline__ void ldsm_x4(uint32_t r[4], uint32_t addr) {
    asm volatile("ldmatrix.sync.aligned.m8n8.x4.shared.b16 {%0,%1,%2,%3}, [%4];"
        : "=r"(r[0]), "=r"(r[1]), "=r"(r[2]), "=r"(r[3]) : "r"(addr));
}

// fp8 e4m3 mma, fp32 accumulate (legacy tensor path, sm_89+)
__device__ __forceinline__ void mma_fp8(float c[4], const uint32_t a[4], const uint32_t b[2])
{
    asm volatile(
        "mma.sync.aligned.m16n8k32.row.col.f32.e4m3.e4m3.f32 "
        "{%0,%1,%2,%3}, {%4,%5,%6,%7}, {%8,%9}, {%0,%1,%2,%3};\n"
        : "+f"(c[0]), "+f"(c[1]), "+f"(c[2]), "+f"(c[3])
        : "r"(a[0]), "r"(a[1]), "r"(a[2]), "r"(a[3]), "r"(b[0]), "r"(b[1]));
}

// ---------------------------------------------------------------------------
// Converts
// ---------------------------------------------------------------------------
__global__ void cvt_s_kernel(const float4* __restrict__ s,
                             const int* __restrict__ lengths)
{
    int i = blockIdx.x * blockDim.x + threadIdx.x;   // N/4 threads
    const int row = i >> 8;          // 256 float4 per 1024-float row
    const int b   = row >> 9;
    const int t   = row & 511;
    const int lim = (lengths[b] + 127) & ~127;
    if (t >= lim) return;
    float4 v = s[i];
    __nv_fp8x2_storage_t lo = __nv_cvt_float2_to_fp8x2(make_float2(v.x, v.y), __NV_SATFINITE, __NV_E4M3);
    __nv_fp8x2_storage_t hi = __nv_cvt_float2_to_fp8x2(make_float2(v.z, v.w), __NV_SATFINITE, __NV_E4M3);
    reinterpret_cast<uint32_t*>(g_s_f8)[i] = (uint32_t)lo | ((uint32_t)hi << 16);
}

__global__ void cvt_w1t_kernel(const float* __restrict__ W1)
{
    __shared__ float tile[32][33];
    const int h0 = blockIdx.x * 32;
    const int k0 = blockIdx.y * 32;
    const int tx = threadIdx.x;      // 32
    const int ty = threadIdx.y;      // 8
#pragma unroll
    for (int i = 0; i < 32; i += 8)
        tile[ty + i][tx] = W1[(size_t)(k0 + ty + i) * H_ + h0 + tx];
    __syncthreads();
#pragma unroll
    for (int i = 0; i < 32; i += 8)
        g_w1t[(size_t)(h0 + ty + i) * S_ + k0 + tx] =
            (uint8_t)__nv_cvt_float_to_fp8(tile[tx][ty + i], __NV_SATFINITE, __NV_E4M3);
}

// ---------------------------------------------------------------------------
// Main GEMM+epilogue. Grid (NHC, NTILES_T, B_); 256 threads = 8 warps (2m x 4n).
// ---------------------------------------------------------------------------
__global__ __launch_bounds__(256, 2)
void traj_main(const float* __restrict__ b1,
               const float* __restrict__ W2,
               const int*   __restrict__ lengths)
{
    const int hc   = blockIdx.x;
    const int tile = blockIdx.y;
    const int b    = blockIdx.z;
    const int t0   = tile * TILE_M;
    if (t0 >= lengths[b]) return;

    extern __shared__ __align__(16) char smem_raw[];
    char* sm = (char*)(((uintptr_t)smem_raw + 127) & ~(uintptr_t)127);
    const uint32_t sb = (uint32_t)__cvta_generic_to_shared(sm);

    const int tid    = threadIdx.x;
    const int wid    = tid >> 5;
    const int lane   = tid & 31;
    const int warp_m = wid >> 2;      // 0..1
    const int warp_n = wid & 3;       // 0..3
    const int g      = lane >> 2;
    const int t4     = lane & 3;
    const int hbase  = hc * TILE_N;

    // --- Affine staging plan (per thread, 8 granules of 16B per stage) ---
    const int srow = tid >> 3;        // 0..31 (+32*i)
    const int sc   = tid & 7;
    const uint8_t* pA0 = g_s_f8 + ((size_t)b * TP1 + t0 + srow) * S_ + sc * 16;
    const uint8_t* pB0 = g_w1t + (size_t)(hbase + srow) * S_ + sc * 16;
    const uint32_t soff0 = (uint32_t)((srow << 7) + ((sc ^ (srow & 7)) << 4));

    // --- ldmatrix per-lane address components ---
    const int sel = lane >> 3;        // 0..3
    const int li  = lane & 7;
    // A: tiles (row-half, k-half): row = warp_m*64 + mt*16 + ((sel&1)<<3) + li ; gran = 2ks + (sel>>1)
    const uint32_t rowA = (uint32_t)(warp_m * 64 + ((sel & 1) << 3) + li);
    const int hiA = sel >> 1;
    // B: tiles (k-half, col-pair): col = warp_n*32 + pair*8 + ((sel>>1)<<3) + li ; gran = 2ks + (sel&1)
    const uint32_t colB = (uint32_t)(warp_n * 32 + ((sel >> 1) << 3) + li);
    const int hiB = sel & 1;

    auto stage = [&](int kt) {
        const uint32_t base = sb + (uint32_t)(kt % NSTAGE) * STAGE_BYTES;
        const int koff = kt * TILE_KB;
#pragma unroll
        for (int i = 0; i < 4; i++)
            cp_async16(base + soff0 + 4096u * i, pA0 + 32768 * i + koff);
#pragma unroll
        for (int i = 0; i < 4; i++)
            cp_async16(base + A_BYTES + soff0 + 4096u * i, pB0 + 32768 * i + koff);
    };

    float C[4][4][4];
#pragma unroll
    for (int mt = 0; mt < 4; mt++)
#pragma unroll
        for (int nt = 0; nt < 4; nt++)
#pragma unroll
            for (int e = 0; e < 4; e++) C[mt][nt][e] = 0.0f;

    stage(0); CP_COMMIT();
    stage(1); CP_COMMIT();

    for (int kt = 0; kt < NKT; kt++) {
        if (kt + 2 < NKT) { stage(kt + 2); CP_COMMIT(); CP_WAIT(2); }
        else if (kt + 1 < NKT) { CP_WAIT(1); }
        else { CP_WAIT(0); }
        __syncthreads();

        const uint32_t Ab = sb + (uint32_t)(kt % NSTAGE) * STAGE_BYTES;
        const uint32_t Bb = Ab + A_BYTES;
        const uint32_t aAddrBase = Ab + (rowA << 7);
        const uint32_t bAddrBase = Bb + (colB << 7);
#pragma unroll
        for (int ks = 0; ks < 4; ks++) {
            const uint32_t swzA = (uint32_t)(((2 * ks + hiA) ^ li) << 4);
            const uint32_t swzB = (uint32_t)(((2 * ks + hiB) ^ li) << 4);
            uint32_t a[4][4], bb0[4], bb1[4];
#pragma unroll
            for (int mt = 0; mt < 4; mt++)
                ldsm_x4(a[mt], aAddrBase + (uint32_t)(mt << 11) + swzA);
            ldsm_x4(bb0, bAddrBase + swzB);                 // nt 0,1
            ldsm_x4(bb1, bAddrBase + (16u << 7) + swzB);    // nt 2,3
#pragma unroll
            for (int mt = 0; mt < 4; mt++) {
                mma_fp8(C[mt][0], a[mt], &bb0[0]);
                mma_fp8(C[mt][1], a[mt], &bb0[2]);
                mma_fp8(C[mt][2], a[mt], &bb1[0]);
                mma_fp8(C[mt][3], a[mt], &bb1[2]);
            }
        }
        __syncthreads();
    }

    // Epilogue: relu(C + b1) * W2[:, 0:4] -> per-thread logits
    float lg[8][4];
#pragma unroll
    for (int r = 0; r < 8; r++)
#pragma unroll
        for (int j = 0; j < 4; j++) lg[r][j] = 0.0f;

#pragma unroll
    for (int nt = 0; nt < 4; nt++) {
        const int h0 = hbase + warp_n * 32 + nt * 8 + t4 * 2;
        const float2 b1v = *reinterpret_cast<const float2*>(&b1[h0]);
        const float4 w2a = *reinterpret_cast<const float4*>(W2 + (size_t)h0 * 32);
        const float4 w2b = *reinterpret_cast<const float4*>(W2 + (size_t)(h0 + 1) * 32);
#pragma unroll
        for (int mt = 0; mt < 4; mt++) {
#pragma unroll
            for (int half = 0; half < 2; half++) {
                const float v0 = fmaxf(C[mt][nt][half * 2 + 0] + b1v.x, 0.0f);
                const float v1 = fmaxf(C[mt][nt][half * 2 + 1] + b1v.y, 0.0f);
                const int rs = mt * 2 + half;
                lg[rs][0] += v0 * w2a.x + v1 * w2b.x;
                lg[rs][1] += v0 * w2a.y + v1 * w2b.y;
                lg[rs][2] += v0 * w2a.z + v1 * w2b.z;
                lg[rs][3] += v0 * w2a.w + v1 * w2b.w;
            }
        }
    }

    // Reduce across t4 lanes, stash per warp_n, then sum 4 warp_n groups
    float* plog = (float*)(sm + OFF_PLOG);   // [4][128][4]
#pragma unroll
    for (int mt = 0; mt < 4; mt++) {
#pragma unroll
        for (int half = 0; half < 2; half++) {
            const int rs  = mt * 2 + half;
            const int row = warp_m * 64 + mt * 16 + half * 8 + g;
#pragma unroll
            for (int j = 0; j < 4; j++) {
                float v = lg[rs][j];
                v += __shfl_xor_sync(0xffffffffu, v, 1);
                v += __shfl_xor_sync(0xffffffffu, v, 2);
                if (t4 == 0) plog[(warp_n * TILE_M + row) * 4 + j] = v;
            }
        }
    }
    __syncthreads();

    if (tid < TILE_M) {
        const int row = tid;
        float4 o;
        o.x = plog[row * 4 + 0] + plog[(TILE_M + row) * 4 + 0] + plog[(2 * TILE_M + row) * 4 + 0] + plog[(3 * TILE_M + row) * 4 + 0];
        o.y = plog[row * 4 + 1] + plog[(TILE_M + row) * 4 + 1] + plog[(2 * TILE_M + row) * 4 + 1] + plog[(3 * TILE_M + row) * 4 + 1];
        o.z = plog[row * 4 + 2] + plog[(TILE_M + row) * 4 + 2] + plog[(2 * TILE_M + row) * 4 + 2] + plog[(3 * TILE_M + row) * 4 + 2];
        o.w = plog[row * 4 + 3] + plog[(TILE_M + row) * 4 + 3] + plog[(2 * TILE_M + row) * 4 + 3] + plog[(3 * TILE_M + row) * 4 + 3];
        const int unit = (b * NTILES_T + tile) * NHC + hc;
        g_plog[(size_t)unit * TILE_M + row] = o;
    }
}

// ---------------------------------------------------------------------------
// Loss: per (b,tile), sum partial logits over 32 hc, logsoftmax, gather, mask.
// ---------------------------------------------------------------------------
__global__ void loss_kernel(const float* __restrict__ b2,
                            const int*   __restrict__ actions,
                            const int*   __restrict__ lengths)
{
    const int tile = blockIdx.x;
    const int b    = blockIdx.y;
    const int pid  = b * NTILES_T + tile;
    const int t0   = tile * TILE_M;
    const int len  = lengths[b];

    float contrib = 0.0f;
    if (t0 < len) {
        const int row = threadIdx.x;
        const int t   = t0 + row;
        if (t < len) {
            float l0 = b2[0], l1 = b2[1], l2 = b2[2], l3 = b2[3];
            const float4* base = g_plog + (size_t)pid * NHC * TILE_M + row;
#pragma unroll
            for (int hc = 0; hc < NHC; hc++) {
                float4 p = base[hc * TILE_M];
                l0 += p.x; l1 += p.y; l2 += p.z; l3 += p.w;
            }
            const int act = actions[b * MAXT + t];
            const float mx  = fmaxf(fmaxf(l0, l1), fmaxf(l2, l3));
            const float lse = mx + logf(expf(l0 - mx) + expf(l1 - mx) + expf(l2 - mx) + expf(l3 - mx));
            const float la  = (act == 0) ? l0 : (act == 1) ? l1 : (act == 2) ? l2 : l3;
            contrib = la - lse;
        }
    }
#pragma unroll
    for (int o = 16; o > 0; o >>= 1) contrib += __shfl_xor_sync(0xffffffffu, contrib, o);
    __shared__ float red[4];
    if ((threadIdx.x & 31) == 0) red[threadIdx.x >> 5] = contrib;
    __syncthreads();
    if (threadIdx.x == 0)
        g_partial[pid] = red[0] + red[1] + red[2] + red[3];
}

// ---------------------------------------------------------------------------
__global__ void finalize_kernel(float* __restrict__ out)
{
    int tid = threadIdx.x;   // 256 threads
    float v = g_partial[tid];
#pragma unroll
    for (int o = 16; o > 0; o >>= 1) v += __shfl_xor_sync(0xffffffffu, v, o);
    __shared__ float red[8];
    if ((tid & 31) == 0) red[tid >> 5] = v;
    __syncthreads();
    if (tid == 0) {
        float s = 0.0f;
        for (int w = 0; w < 8; w++) s += red[w];
        out[0] = -s;
    }
}

// ---------------------------------------------------------------------------
extern "C" void kernel_launch(void* const* d_in, const int* in_sizes, int n_in,
                              void* d_out, int out_size)
{
    const float* s       = (const float*)d_in[0];
    const int*   actions = (const int*)  d_in[1];
    const int*   lengths = (const int*)  d_in[2];
    const float* W1      = (const float*)d_in[3];
    const float* b1      = (const float*)d_in[4];
    const float* W2      = (const float*)d_in[5];
    const float* b2      = (const float*)d_in[6];
    float* out = (float*)d_out;

    cudaFuncSetAttribute(traj_main, cudaFuncAttributeMaxDynamicSharedMemorySize, SMEM_BYTES);

    cvt_s_kernel<<<32768, 256>>>((const float4*)s, lengths);
    cvt_w1t_kernel<<<dim3(H_ / 32, S_ / 32), dim3(32, 8)>>>(W1);
    traj_main<<<dim3(NHC, NTILES_T, B_), 256, SMEM_BYTES>>>(b1, W2, lengths);
    loss_kernel<<<dim3(NTILES_T, B_), 128>>>(b2, actions, lengths);
    finalize_kernel<<<1, 256>>>(out);
}